// round 16
// baseline (speedup 1.0000x reference)
#include <cuda_runtime.h>
#include <cuda_fp16.h>
#include <math.h>
#include <stdint.h>

#define NN 60000
#define EE 300000
#define AA 8000
#define GG 256
#define DD 128
#define HH 8
#define CC 16
#define LL 3
#define RBFD 16
#define SBFD 112

// ---------------- scratch (static device globals; no allocation) ----------------
__device__ float g_featA[NN * DD];
__device__ float g_featB[NN * DD];
__device__ float g_featC[NN * DD];
__device__ float g_featD[NN * DD];
__device__ float g_featE[NN * DD];
__device__ float g_featF[NN * DD];
__device__ uint32_t g_swh[(size_t)EE * 64];   // CSR-ordered sbf weights, half2-packed
__device__ float g_at2[AA * DD];
__device__ float g_at3[AA * DD];
__device__ float g_at4[AA * DD];
__device__ float g_at5[AA * DD];
__device__ float g_at6[AA * DD];
__device__ float g_results[AA];
__device__ float g_gsum[LL * GG];
__device__ float g_gsq[LL * GG];
__device__ float g_gcnt[GG];
__device__ float g_wfold[LL * DD * DD];
__device__ float g_bfold[LL * DD];
__device__ int g_eoff[NN + 1];
__device__ int g_epos[NN];
__device__ int g_ecsr[EE];
__device__ int g_pinv[EE];
__device__ int g_esrcc[EE];
__device__ int g_paic[EE];
__device__ int g_aoff[AA + 1];
__device__ int g_apos[AA];
__device__ int g_acsr[NN];

// ---------------- helpers ----------------
__device__ __forceinline__ float silu_f(float v) { return v / (1.f + expf(-v)); }

__device__ __forceinline__ uint32_t pack_h2(float x, float y) {
    __half2 h = __floats2half2_rn(x, y);
    return *(uint32_t*)&h;
}
__device__ __forceinline__ float h2_lo(uint32_t u) {
    __half2 h = *(__half2*)&u;
    return __low2float(h);
}
__device__ __forceinline__ float h2_hi(uint32_t u) {
    __half2 h = *(__half2*)&u;
    return __high2float(h);
}
__device__ __forceinline__ float4 unp4(uint2 u) {
    return make_float4(h2_lo(u.x), h2_hi(u.x), h2_lo(u.y), h2_hi(u.y));
}

__device__ __forceinline__ void mma_f16(float* acc, const uint32_t* a, const uint32_t* b) {
    asm volatile(
        "mma.sync.aligned.m16n8k16.row.col.f32.f16.f16.f32 "
        "{%0,%1,%2,%3}, {%4,%5,%6,%7}, {%8,%9}, {%0,%1,%2,%3};\n"
        : "+f"(acc[0]), "+f"(acc[1]), "+f"(acc[2]), "+f"(acc[3])
        : "r"(a[0]), "r"(a[1]), "r"(a[2]), "r"(a[3]), "r"(b[0]), "r"(b[1]));
}

__device__ __forceinline__ uint32_t sptr(const void* p) {
    return (uint32_t)__cvta_generic_to_shared(p);
}
#define LDSM4(r0, r1, r2, r3, addr)                                              \
    asm volatile("ldmatrix.sync.aligned.m8n8.x4.shared.b16 {%0,%1,%2,%3}, [%4];" \
                 : "=r"(r0), "=r"(r1), "=r"(r2), "=r"(r3) : "r"(addr))

#define EP_SILU 1
#define EP_RES 2
#define EP_MUL 4
#define EP_GNA 8
#define EP_GNRES 16
#define EP_PERM 32
#define EP_HOUT 64  // store output as packed half2 (C is uint32*, 64 words/row)

// ---------------- templated fp16 split tensor-core GEMM, N = 128 --------------
// T3: 3-term (ah*wh + ah*wl + al*wh); else 2-term (ah*wh + al*wh).
struct GD { const float *A, *W, *bias, *res, *mul; float* C; const int* perm; int M, K; };
struct GB3 { GD d[3]; };

#define SAW 12

template <bool T3, int F>
__global__ __launch_bounds__(256, 2) void gemm_t(
    GB3 gb, const int* __restrict__ gnb, const float* __restrict__ gcnt,
    const float* __restrict__ gsumP, const float* __restrict__ gsqP)
{
    __shared__ uint32_t AsH[2][128][SAW];
    __shared__ uint32_t AsL[2][128][SAW];
    __shared__ uint32_t WsH[2][128][SAW];
    __shared__ uint32_t WsL[2][128][SAW];

    const GD d = gb.d[blockIdx.y];
    const int row0 = blockIdx.x * 128;

    const int tid = threadIdx.x;
    const int wid = tid >> 5, lane = tid & 31;
    const int g = lane >> 2, tig = lane & 3;
    const int m0 = (wid & 1) * 64, n0 = (wid >> 1) * 32;

    const int arow = tid >> 1, akf = (tid & 1) * 8, akw = (tid & 1) * 4;
    const int wn = tid & 127, wkb = (tid >> 7) * 8, wkw = (tid >> 7) * 4;
    const int a_r = lane & 15, a_kw = (lane >> 4) * 4;
    const int b_nadd = ((lane >> 4) << 3) | (lane & 7), b_kw = ((lane >> 3) & 1) * 4;

    float acc[4][4][4];
#pragma unroll
    for (int mi = 0; mi < 4; mi++)
#pragma unroll
        for (int ni = 0; ni < 4; ni++)
#pragma unroll
            for (int r = 0; r < 4; r++) acc[mi][ni][r] = 0.f;

    const int nc = d.K >> 4;
    const bool arow_ok = (row0 + arow) < d.M;
    const float* aptr = d.A + (size_t)(row0 + arow) * d.K + akf;

    float amean = 0.f, ars = 1.f;
    if constexpr (F & EP_GNA) {
        if (arow_ok) {
            int gg = gnb[row0 + arow];
            float inv = 1.f / (gcnt[gg] * 128.f);
            amean = gsumP[gg] * inv;
            float var = gsqP[gg] * inv - amean * amean;
            ars = rsqrtf(var + 1e-8f);
        }
    }

    float fa[8], fw[8];
    auto fetch = [&](int c) {
        const float* ap = aptr + (size_t)c * 16;
        if (arow_ok) {
            *(float4*)&fa[0] = *(const float4*)ap;
            *(float4*)&fa[4] = *(const float4*)(ap + 4);
        } else {
#pragma unroll
            for (int p = 0; p < 8; p++) fa[p] = 0.f;
        }
        if constexpr (F & EP_GNA) {
#pragma unroll
            for (int p = 0; p < 8; p++) fa[p] = (fa[p] - amean) * ars;
        }
        const float* wp = d.W + (size_t)c * 16 * 128;
#pragma unroll
        for (int j = 0; j < 8; j++) fw[j] = wp[(size_t)(wkb + j) * 128 + wn];
    };
    auto stage = [&](int b) {
        uint32_t h[4], l[4];
#pragma unroll
        for (int p = 0; p < 4; p++) {
            h[p] = pack_h2(fa[2 * p], fa[2 * p + 1]);
            l[p] = pack_h2(fa[2 * p] - h2_lo(h[p]), fa[2 * p + 1] - h2_hi(h[p]));
        }
        *(uint4*)&AsH[b][arow][akw] = make_uint4(h[0], h[1], h[2], h[3]);
        *(uint4*)&AsL[b][arow][akw] = make_uint4(l[0], l[1], l[2], l[3]);
#pragma unroll
        for (int p = 0; p < 4; p++) h[p] = pack_h2(fw[2 * p], fw[2 * p + 1]);
        *(uint4*)&WsH[b][wn][wkw] = make_uint4(h[0], h[1], h[2], h[3]);
        if constexpr (T3) {
#pragma unroll
            for (int p = 0; p < 4; p++)
                l[p] = pack_h2(fw[2 * p] - h2_lo(h[p]), fw[2 * p + 1] - h2_hi(h[p]));
            *(uint4*)&WsL[b][wn][wkw] = make_uint4(l[0], l[1], l[2], l[3]);
        }
    };

    fetch(0);
    stage(0);
    __syncthreads();

    int cur = 0;
    for (int c = 0; c < nc; c++) {
        const bool pf = (c + 1 < nc);
        if (pf) fetch(c + 1);
        uint32_t bH[4][2], bL[4][2];
#pragma unroll
        for (int hh = 0; hh < 2; hh++) {
            int n = n0 + hh * 16 + b_nadd;
            LDSM4(bH[2 * hh][0], bH[2 * hh][1], bH[2 * hh + 1][0], bH[2 * hh + 1][1],
                  sptr(&WsH[cur][n][b_kw]));
            if constexpr (T3)
                LDSM4(bL[2 * hh][0], bL[2 * hh][1], bL[2 * hh + 1][0], bL[2 * hh + 1][1],
                      sptr(&WsL[cur][n][b_kw]));
        }
#pragma unroll
        for (int mi = 0; mi < 4; mi++) {
            int r = m0 + mi * 16 + a_r;
            uint32_t aH[4], aL[4];
            LDSM4(aH[0], aH[1], aH[2], aH[3], sptr(&AsH[cur][r][a_kw]));
            LDSM4(aL[0], aL[1], aL[2], aL[3], sptr(&AsL[cur][r][a_kw]));
#pragma unroll
            for (int ni = 0; ni < 4; ni++) {
                mma_f16(acc[mi][ni], aH, bH[ni]);
                if constexpr (T3) mma_f16(acc[mi][ni], aH, bL[ni]);
                mma_f16(acc[mi][ni], aL, bH[ni]);
            }
        }
        if (pf) stage(cur ^ 1);
        __syncthreads();
        cur ^= 1;
    }

    // ---- epilogue: (mi, half) outer, per-row params computed once ----
#pragma unroll
    for (int mi = 0; mi < 4; mi++) {
#pragma unroll
        for (int half = 0; half < 2; half++) {
            int r = row0 + m0 + mi * 16 + g + half * 8;
            bool rok = r < d.M;
            float rmean = 0.f, rrs = 1.f;
            if constexpr (F & EP_GNRES) {
                if (rok) {
                    int gg = gnb[r];
                    float inv = 1.f / (gcnt[gg] * 128.f);
                    rmean = gsumP[gg] * inv;
                    float var = gsqP[gg] * inv - rmean * rmean;
                    rrs = rsqrtf(var + 1e-8f);
                }
            }
#pragma unroll
            for (int ni = 0; ni < 4; ni++) {
                int cidx = n0 + ni * 8 + tig * 2;
                float vx = acc[mi][ni][half * 2 + 0];
                float vy = acc[mi][ni][half * 2 + 1];
                if (d.bias) { vx += d.bias[cidx]; vy += d.bias[cidx + 1]; }
                if constexpr (F & EP_SILU) { vx = silu_f(vx); vy = silu_f(vy); }
                if (rok) {
                    size_t off = (size_t)r * 128 + cidx;
                    if constexpr (F & EP_RES) {
                        float2 rr = *(const float2*)(d.res + off);
                        if constexpr (F & EP_GNRES) {
                            rr.x = (rr.x - rmean) * rrs;
                            rr.y = (rr.y - rmean) * rrs;
                        }
                        vx += rr.x; vy += rr.y;
                    }
                    if constexpr (F & EP_MUL) {
                        if (d.mul) {
                            float2 mm = *(const float2*)(d.mul + off);
                            vx *= mm.x; vy *= mm.y;
                        }
                    }
                    size_t orow;
                    if constexpr (F & EP_PERM) orow = (size_t)d.perm[r];
                    else orow = (size_t)r;
                    if constexpr (F & EP_HOUT) {
                        ((uint32_t*)d.C)[orow * 64 + (cidx >> 1)] = pack_h2(vx, vy);
                    } else {
                        *(float2*)(d.C + orow * 128 + cidx) = make_float2(vx, vy);
                    }
                }
            }
        }
    }
}

// ---------------- fp32 weight fold: W' = w2@we, b' = b2@we (per layer) --------
__global__ void fold_we(const float* __restrict__ w2, const float* __restrict__ b2,
                        const float* __restrict__ we, float* __restrict__ Wf,
                        float* __restrict__ Bf) {
    int l = blockIdx.y, r = blockIdx.x, c = threadIdx.x;
    const float* W2 = w2 + (size_t)l * DD * DD;
    const float* WE = we + (size_t)l * DD * DD;
    float s = 0.f;
    for (int k = 0; k < DD; k++) s += W2[r * DD + k] * WE[k * DD + c];
    Wf[(size_t)l * DD * DD + r * DD + c] = s;
    if (r == 0) {
        const float* B2 = b2 + (size_t)l * DD;
        float t = 0.f;
        for (int k = 0; k < DD; k++) t += B2[k] * WE[k * DD + c];
        Bf[(size_t)l * DD + c] = t;
    }
}

// ---------------- CSR construction ----------------
__global__ void hist_seg(const int* __restrict__ idx, int n, int* __restrict__ deg) {
    int t = blockIdx.x * blockDim.x + threadIdx.x;
    if (t >= n) return;
    atomicAdd(&deg[idx[t] + 1], 1);
}

__global__ void scan_offsets(int* __restrict__ deg, int n) {
    __shared__ int wsum[32];
    __shared__ int carry;
    const int lane = threadIdx.x & 31, w = threadIdx.x >> 5;
    if (threadIdx.x == 0) carry = 0;
    __syncthreads();
    for (int base = 0; base < n; base += 1024) {
        int i = base + threadIdx.x;
        int v = (i < n) ? deg[i + 1] : 0;
        int s = v;
#pragma unroll
        for (int o = 1; o < 32; o <<= 1) {
            int t = __shfl_up_sync(0xffffffffu, s, o);
            if (lane >= o) s += t;
        }
        if (lane == 31) wsum[w] = s;
        __syncthreads();
        if (w == 0) {
            int ws = wsum[lane];
#pragma unroll
            for (int o = 1; o < 32; o <<= 1) {
                int t = __shfl_up_sync(0xffffffffu, ws, o);
                if (lane >= o) ws += t;
            }
            wsum[lane] = ws;
        }
        __syncthreads();
        int total = wsum[31];
        int off = carry + (w ? wsum[w - 1] : 0);
        if (i < n) deg[i + 1] = s + off;
        __syncthreads();
        if (threadIdx.x == 0) carry += total;
        __syncthreads();
    }
}

__global__ void fill_csr(const int* __restrict__ idx, int n, int* __restrict__ pos,
                         int* __restrict__ csr, int* __restrict__ pinv) {
    int t = blockIdx.x * blockDim.x + threadIdx.x;
    if (t >= n) return;
    int p = atomicAdd(&pos[idx[t]], 1);
    csr[p] = t;
    if (pinv) pinv[t] = p;
}

__global__ void perm_edges(const int* __restrict__ ecsr, const int* __restrict__ esrc,
                           const int* __restrict__ pai, int* __restrict__ esrc_c,
                           int* __restrict__ pai_c) {
    int j = blockIdx.x * blockDim.x + threadIdx.x;
    if (j >= EE) return;
    int e = ecsr[j];
    esrc_c[j] = esrc[e];
    pai_c[j] = pai[e];
}

// ---------------- dual CSR gather ----------------
struct GPair { const float* src; float* dst; };

__global__ void gather2(GPair p0, GPair p1, const int* __restrict__ off,
                        const int* __restrict__ csr) {
    GPair p = blockIdx.y ? p1 : p0;
    int idx = blockIdx.x * blockDim.x + threadIdx.x;
    int w = idx >> 5, lane = idx & 31;
    if (w >= AA) return;
    int s = off[w], e = off[w + 1];
    float4 acc = make_float4(0, 0, 0, 0);
    for (int j = s; j < e; j++) {
        int n = csr[j];
        float4 v = ((const float4*)(p.src + (size_t)n * DD))[lane];
        acc.x += v.x; acc.y += v.y; acc.z += v.z; acc.w += v.w;
    }
    ((float4*)(p.dst + (size_t)w * DD))[lane] = acc;
}

// ---------------- fused CSR attention: single pass + gate + gn stats ----------
// k, v, ek, sw are half2-packed (64 words/row). q fp32. io holds the per-node
// gate (rbf@wrbf) on input; overwritten with gated output.
__global__ void attn_csr(const float* __restrict__ q, const uint32_t* __restrict__ k,
                         const uint32_t* __restrict__ v, const uint32_t* __restrict__ ek,
                         const uint32_t* __restrict__ swc, const int* __restrict__ esrc_c,
                         const int* __restrict__ pai_c, const int* __restrict__ off,
                         float* __restrict__ io, const int* __restrict__ nb,
                         float* __restrict__ gs, float* __restrict__ gq) {
    int idx = blockIdx.x * blockDim.x + threadIdx.x;
    int w = idx >> 5, lane = idx & 31;
    if (w >= NN) return;
    int s0 = off[w], s1 = off[w + 1];
    float4 q4 = ((const float4*)(q + (size_t)w * DD))[lane];

    float4 acc = make_float4(0, 0, 0, 0);
    float den = 0.f;
    for (int j = s0; j < s1; j++) {
        int sn = esrc_c[j], pa = pai_c[j];
        float4 k4 = unp4(((const uint2*)(k + (size_t)sn * 64))[lane]);
        float4 e4 = unp4(((const uint2*)(ek + (size_t)pa * 64))[lane]);
        float p = q4.x * (k4.x + e4.x) + q4.y * (k4.y + e4.y) +
                  q4.z * (k4.z + e4.z) + q4.w * (k4.w + e4.w);
        p += __shfl_xor_sync(0xffffffffu, p, 1);
        p += __shfl_xor_sync(0xffffffffu, p, 2);
        float ex = expf(p * 0.25f);
        den += ex;
        float4 v4 = unp4(((const uint2*)(v + (size_t)sn * 64))[lane]);
        float4 s4 = unp4(((const uint2*)(swc + (size_t)j * 64))[lane]);
        acc.x += ex * (v4.x + e4.x) * s4.x;
        acc.y += ex * (v4.y + e4.y) * s4.y;
        acc.z += ex * (v4.z + e4.z) * s4.z;
        acc.w += ex * (v4.w + e4.w) * s4.w;
    }
    float inv = 1.f / (den + 1e-16f);
    float4 g4 = ((const float4*)(io + (size_t)w * DD))[lane];
    float4 o;
    o.x = acc.x * inv * g4.x;
    o.y = acc.y * inv * g4.y;
    o.z = acc.z * inv * g4.z;
    o.w = acc.w * inv * g4.w;
    ((float4*)(io + (size_t)w * DD))[lane] = o;

    float s = o.x + o.y + o.z + o.w;
    float qq = o.x * o.x + o.y * o.y + o.z * o.z + o.w * o.w;
#pragma unroll
    for (int t = 16; t; t >>= 1) {
        s += __shfl_xor_sync(0xffffffffu, s, t);
        qq += __shfl_xor_sync(0xffffffffu, qq, t);
    }
    if (!lane) {
        int gg = nb[w];
        atomicAdd(&gs[gg], s);
        atomicAdd(&gq[gg], qq);
    }
}

// ---------------- misc kernels ----------------
__global__ void count_nodes(const int* __restrict__ batch, float* __restrict__ cnt) {
    int n = blockIdx.x * blockDim.x + threadIdx.x;
    if (n >= NN) return;
    atomicAdd(&cnt[batch[n]], 1.f);
}

__global__ void read_dot(const float* __restrict__ a, const float* __restrict__ w3,
                         const float* __restrict__ b3, float* __restrict__ results) {
    int idx = blockIdx.x * blockDim.x + threadIdx.x;
    int warp = idx >> 5, lane = idx & 31;
    if (warp >= AA) return;
    float4 av = ((const float4*)(a + (size_t)warp * DD))[lane];
    float4 wv = ((const float4*)w3)[lane];
    float s = av.x * wv.x + av.y * wv.y + av.z * wv.z + av.w * wv.w;
#pragma unroll
    for (int o = 16; o; o >>= 1) s += __shfl_xor_sync(0xffffffffu, s, o);
    if (!lane) results[warp] += s + b3[0];
}

__global__ void final_scatter(const float* __restrict__ results, const int* __restrict__ abatch,
                              float* __restrict__ out) {
    int a = blockIdx.x * blockDim.x + threadIdx.x;
    if (a >= AA) return;
    atomicAdd(&out[abatch[a]], results[a] * (1.0f / (float)LL));
}

// ---------------- host orchestration ----------------
static GD mkd(const float* A, const float* W, const float* bias, const float* res,
              const float* mul, float* C, const int* perm, int M, int K) {
    GD d; d.A = A; d.W = W; d.bias = bias; d.res = res; d.mul = mul;
    d.C = C; d.perm = perm; d.M = M; d.K = K; return d;
}

template <bool T3, int F>
static void glaunch(const GD& d0, const int* gnb = nullptr, const float* gcnt = nullptr,
                    const float* gs = nullptr, const float* gq = nullptr) {
    GB3 gb; gb.d[0] = d0;
    gemm_t<T3, F><<<dim3((d0.M + 127) / 128, 1), 256>>>(gb, gnb, gcnt, gs, gq);
}
template <bool T3, int F>
static void glaunchN(const GD* ds, int n) {
    GB3 gb;
    for (int i = 0; i < n; i++) gb.d[i] = ds[i];
    gemm_t<T3, F><<<dim3((ds[0].M + 127) / 128, n), 256>>>(gb, nullptr, nullptr,
                                                           nullptr, nullptr);
}

extern "C" void kernel_launch(void* const* d_in, const int* in_sizes, int n_in,
                              void* d_out, int out_size) {
    const float* x         = (const float*)d_in[0];
    const float* node_rbf  = (const float*)d_in[1];
    const float* edge_sbf  = (const float*)d_in[2];
    const int*   eidx      = (const int*)d_in[3];
    const int*   pai       = (const int*)d_in[4];
    const int*   idx0      = (const int*)d_in[5];
    const int*   abatch    = (const int*)d_in[6];
    const int*   nbatch    = (const int*)d_in[7];
    const float* edgenn_w1 = (const float*)d_in[8];
    const float* edgenn_b1 = (const float*)d_in[9];
    const float* edgenn_w2 = (const float*)d_in[10];
    const float* edgenn_b2 = (const float*)d_in[11];
    const float* conv_wq   = (const float*)d_in[12];
    const float* conv_wk   = (const float*)d_in[13];
    const float* conv_wv   = (const float*)d_in[14];
    const float* conv_we   = (const float*)d_in[15];
    const float* conv_wsbf = (const float*)d_in[16];
    const float* conv_bsbf = (const float*)d_in[17];
    const float* conv_wrbf = (const float*)d_in[18];
    const float* dense_w   = (const float*)d_in[19];
    const float* dense_b   = (const float*)d_in[20];
    const float* bf_w      = (const float*)d_in[21];
    const float* bf_b      = (const float*)d_in[22];
    const float* af_w      = (const float*)d_in[23];
    const float* af_b      = (const float*)d_in[24];
    const float* read_wrbf = (const float*)d_in[25];
    const float* read_w1   = (const float*)d_in[26];
    const float* read_b1   = (const float*)d_in[27];
    const float* read_w2   = (const float*)d_in[28];
    const float* read_b2   = (const float*)d_in[29];
    const float* read_w3   = (const float*)d_in[30];
    const float* read_b3   = (const float*)d_in[31];

    float *featA, *featB, *featC, *featD, *featE, *featF;
    uint32_t* swh;
    float *at2, *at3, *at4, *at5, *at6, *results, *gsum, *gsq, *gcnt, *wfold, *bfold;
    int *eoff, *epos, *ecsr, *pinv, *esrcc, *paic, *aoff, *apos, *acsr;
    cudaGetSymbolAddress((void**)&featA, g_featA);
    cudaGetSymbolAddress((void**)&featB, g_featB);
    cudaGetSymbolAddress((void**)&featC, g_featC);
    cudaGetSymbolAddress((void**)&featD, g_featD);
    cudaGetSymbolAddress((void**)&featE, g_featE);
    cudaGetSymbolAddress((void**)&featF, g_featF);
    cudaGetSymbolAddress((void**)&swh, g_swh);
    cudaGetSymbolAddress((void**)&at2, g_at2);
    cudaGetSymbolAddress((void**)&at3, g_at3);
    cudaGetSymbolAddress((void**)&at4, g_at4);
    cudaGetSymbolAddress((void**)&at5, g_at5);
    cudaGetSymbolAddress((void**)&at6, g_at6);
    cudaGetSymbolAddress((void**)&results, g_results);
    cudaGetSymbolAddress((void**)&gsum, g_gsum);
    cudaGetSymbolAddress((void**)&gsq, g_gsq);
    cudaGetSymbolAddress((void**)&gcnt, g_gcnt);
    cudaGetSymbolAddress((void**)&wfold, g_wfold);
    cudaGetSymbolAddress((void**)&bfold, g_bfold);
    cudaGetSymbolAddress((void**)&eoff, g_eoff);
    cudaGetSymbolAddress((void**)&epos, g_epos);
    cudaGetSymbolAddress((void**)&ecsr, g_ecsr);
    cudaGetSymbolAddress((void**)&pinv, g_pinv);
    cudaGetSymbolAddress((void**)&esrcc, g_esrcc);
    cudaGetSymbolAddress((void**)&paic, g_paic);
    cudaGetSymbolAddress((void**)&aoff, g_aoff);
    cudaGetSymbolAddress((void**)&apos, g_apos);
    cudaGetSymbolAddress((void**)&acsr, g_acsr);

    cudaMemsetAsync(results, 0, AA * sizeof(float));
    cudaMemsetAsync(gcnt, 0, GG * sizeof(float));
    cudaMemsetAsync(gsum, 0, LL * GG * sizeof(float));
    cudaMemsetAsync(gsq, 0, LL * GG * sizeof(float));
    cudaMemsetAsync(d_out, 0, GG * sizeof(float));
    count_nodes<<<(NN + 255) / 256, 256>>>(nbatch, gcnt);

    // ---- build CSRs ----
    cudaMemsetAsync(eoff, 0, (NN + 1) * sizeof(int));
    hist_seg<<<(EE + 255) / 256, 256>>>(eidx + EE, EE, eoff);
    scan_offsets<<<1, 1024>>>(eoff, NN);
    cudaMemcpyAsync(epos, eoff, NN * sizeof(int), cudaMemcpyDeviceToDevice);
    fill_csr<<<(EE + 255) / 256, 256>>>(eidx + EE, EE, epos, ecsr, pinv);
    perm_edges<<<(EE + 255) / 256, 256>>>(ecsr, eidx, pai, esrcc, paic);

    cudaMemsetAsync(aoff, 0, (AA + 1) * sizeof(int));
    hist_seg<<<(NN + 255) / 256, 256>>>(idx0, NN, aoff);
    scan_offsets<<<1, 1024>>>(aoff, AA);
    cudaMemcpyAsync(apos, aoff, AA * sizeof(int), cudaMemcpyDeviceToDevice);
    fill_csr<<<(NN + 255) / 256, 256>>>(idx0, NN, apos, acsr, (int*)nullptr);

    // ---- fold edgenn_w2 @ conv_we per layer (fp32 exact) ----
    fold_we<<<dim3(DD, LL), DD>>>(edgenn_w2, edgenn_b2, conv_we, wfold, bfold);

    const float* cur = x;

    for (int i = 0; i < LL; i++) {
        size_t dd = (size_t)i * DD * DD;
        float* kt = (cur == featC) ? featD : featC;
        float* gs = gsum + (size_t)i * GG;
        float* gq = gsq + (size_t)i * GG;
        // half2 views: kh lives in kt's memory (overwritten later by bf1 output),
        // vh in featE, ekh in at3 — lifetimes verified (consumed by attn only).
        uint32_t* kh = (uint32_t*)kt;
        uint32_t* vh = (uint32_t*)featE;
        uint32_t* ekh = (uint32_t*)at3;

        // 1) k, v batched -> half2
        {
            GD ds[2] = {
                mkd(cur, conv_wk + dd, nullptr, nullptr, nullptr, (float*)kh, nullptr, NN, DD),
                mkd(cur, conv_wv + dd, nullptr, nullptr, nullptr, (float*)vh, nullptr, NN, DD)};
            glaunchN<true, EP_HOUT>(ds, 2);
        }
        // 2) q + gates batched (EP_MUL null-checks mul): q->featA, wrbf->featB, read-gate->featF
        {
            GD ds[3] = {
                mkd(cur, conv_wq + dd, nullptr, nullptr, nullptr, featA, nullptr, NN, DD),
                mkd(node_rbf, conv_wrbf + (size_t)i * RBFD * DD, nullptr, nullptr,
                    nullptr, featB, nullptr, NN, RBFD),
                mkd(node_rbf, read_wrbf + (size_t)i * RBFD * DD, nullptr, nullptr,
                    cur, featF, nullptr, NN, RBFD)};
            glaunchN<true, EP_MUL>(ds, 3);
        }
        // 3) sbf (2-term, CSR-permuted rows, half2 output) -> swh
        glaunch<false, EP_PERM | EP_HOUT>(
            mkd(edge_sbf, conv_wsbf + (size_t)i * SBFD * DD, conv_bsbf + (size_t)i * DD,
                nullptr, nullptr, (float*)swh, pinv, EE, SBFD));
        // 4) dual gather: cur -> at6 (edge path), featF -> at4 (readout)
        {
            GPair p0 = {cur, at6}, p1 = {featF, at4};
            gather2<<<dim3((AA * 32 + 255) / 256, 2), 256>>>(p0, p1, aoff, acsr);
        }
        // 5) AA batch: edgenn_w1 -> at2 ; read_w1 -> at5 (both SILU)
        {
            GD ds[2] = {
                mkd(at6, edgenn_w1 + dd, edgenn_b1 + (size_t)i * DD, nullptr, nullptr,
                    at2, nullptr, AA, DD),
                mkd(at4, read_w1 + (size_t)i * DD * DD, read_b1 + (size_t)i * DD,
                    nullptr, nullptr, at5, nullptr, AA, DD)};
            glaunchN<true, EP_SILU>(ds, 2);
        }
        // 6) wfold -> ekh (half2) ; read_w2 (SILU) -> at6 ; dot(w3) -> results
        glaunch<true, EP_HOUT>(mkd(at2, wfold + dd, bfold + (size_t)i * DD, nullptr,
                                   nullptr, (float*)ekh, nullptr, AA, DD));
        glaunch<true, EP_SILU>(mkd(at5, read_w2 + (size_t)i * DD * DD,
                                   read_b2 + (size_t)i * DD, nullptr, nullptr, at6,
                                   nullptr, AA, DD));
        read_dot<<<(AA * 32 + 255) / 256, 256>>>(at6, read_w3 + (size_t)i * DD,
                                                 read_b3 + i, results);
        // 7) attention (gate mul + gn stats fused) -> featB in place
        attn_csr<<<(NN * 32 + 255) / 256, 256>>>(featA, kh, vh, ekh, swh,
                                                 esrcc, paic, eoff, featB, nbatch, gs, gq);
        // 8) residual chain (gn fused: bf1 fetch, bf2 residual)
        glaunch<true, EP_SILU | EP_GNA>(
            mkd(featB, bf_w + (size_t)(i * 2 + 0) * DD * DD, bf_b + (size_t)(i * 2 + 0) * DD,
                nullptr, nullptr, kt, nullptr, NN, DD), nbatch, gcnt, gs, gq);
        glaunch<true, EP_SILU | EP_RES | EP_GNRES>(
            mkd(kt, bf_w + (size_t)(i * 2 + 1) * DD * DD, bf_b + (size_t)(i * 2 + 1) * DD,
                featB, nullptr, featB, nullptr, NN, DD), nbatch, gcnt, gs, gq);
        glaunch<true, EP_SILU | EP_RES>(
            mkd(featB, dense_w + dd, dense_b + (size_t)i * DD, cur, nullptr, kt,
                nullptr, NN, DD));
        glaunch<true, EP_SILU>(
            mkd(kt, af_w + (size_t)(i * 4 + 0) * DD * DD, af_b + (size_t)(i * 4 + 0) * DD,
                nullptr, nullptr, featB, nullptr, NN, DD));
        glaunch<true, EP_SILU | EP_RES>(
            mkd(featB, af_w + (size_t)(i * 4 + 1) * DD * DD, af_b + (size_t)(i * 4 + 1) * DD,
                kt, nullptr, kt, nullptr, NN, DD));
        glaunch<true, EP_SILU>(
            mkd(kt, af_w + (size_t)(i * 4 + 2) * DD * DD, af_b + (size_t)(i * 4 + 2) * DD,
                nullptr, nullptr, featB, nullptr, NN, DD));
        glaunch<true, EP_SILU | EP_RES>(
            mkd(featB, af_w + (size_t)(i * 4 + 3) * DD * DD, af_b + (size_t)(i * 4 + 3) * DD,
                kt, nullptr, kt, nullptr, NN, DD));
        cur = kt;
    }

    // ---- final readout(LL) ----
    glaunch<true, EP_MUL>(mkd(node_rbf, read_wrbf + (size_t)LL * RBFD * DD, nullptr,
                              nullptr, cur, featF, nullptr, NN, RBFD));
    {
        GPair p0 = {featF, at4}, p1 = {featF, at4};
        gather2<<<dim3((AA * 32 + 255) / 256, 1), 256>>>(p0, p1, aoff, acsr);
    }
    glaunch<true, EP_SILU>(mkd(at4, read_w1 + (size_t)LL * DD * DD,
                               read_b1 + (size_t)LL * DD, nullptr, nullptr, at5,
                               nullptr, AA, DD));
    glaunch<true, EP_SILU>(mkd(at5, read_w2 + (size_t)LL * DD * DD,
                               read_b2 + (size_t)LL * DD, nullptr, nullptr, at6,
                               nullptr, AA, DD));
    read_dot<<<(AA * 32 + 255) / 256, 256>>>(at6, read_w3 + (size_t)LL * DD,
                                             read_b3 + LL, results);

    final_scatter<<<(AA + 255) / 256, 256>>>(results, abatch, (float*)d_out);
}

// round 17
// speedup vs baseline: 1.0308x; 1.0308x over previous
#include <cuda_runtime.h>
#include <cuda_fp16.h>
#include <math.h>
#include <stdint.h>

#define NN 60000
#define EE 300000
#define AA 8000
#define GG 256
#define DD 128
#define HH 8
#define CC 16
#define LL 3
#define RBFD 16
#define SBFD 112

// ---------------- scratch (static device globals; no allocation) ----------------
__device__ float g_featA[NN * DD];
__device__ float g_featB[NN * DD];
__device__ float g_featC[NN * DD];
__device__ float g_featD[NN * DD];
__device__ float g_featE[NN * DD];
__device__ float g_featF[NN * DD];
__device__ uint32_t g_swh[(size_t)EE * 64];   // CSR-ordered sbf weights, half2-packed
__device__ float g_at2[AA * DD];
__device__ float g_at3[AA * DD];
__device__ float g_at4[AA * DD];
__device__ float g_at5[AA * DD];
__device__ float g_at6[AA * DD];
__device__ float g_results[AA];
__device__ float g_gsum[LL * GG];
__device__ float g_gsq[LL * GG];
__device__ float g_gcnt[GG];
__device__ float g_wfold[LL * DD * DD];
__device__ float g_bfold[LL * DD];
__device__ int g_eoff[NN + 1];
__device__ int g_epos[NN];
__device__ int g_ecsr[EE];
__device__ int g_pinv[EE];
__device__ int g_esrcc[EE];
__device__ int g_paic[EE];
__device__ int g_aoff[AA + 1];
__device__ int g_apos[AA];
__device__ int g_acsr[NN];

// ---------------- helpers ----------------
__device__ __forceinline__ float silu_f(float v) { return v / (1.f + expf(-v)); }

__device__ __forceinline__ uint32_t pack_h2(float x, float y) {
    __half2 h = __floats2half2_rn(x, y);
    return *(uint32_t*)&h;
}
__device__ __forceinline__ float h2_lo(uint32_t u) {
    __half2 h = *(__half2*)&u;
    return __low2float(h);
}
__device__ __forceinline__ float h2_hi(uint32_t u) {
    __half2 h = *(__half2*)&u;
    return __high2float(h);
}
__device__ __forceinline__ float4 unp4(uint2 u) {
    return make_float4(h2_lo(u.x), h2_hi(u.x), h2_lo(u.y), h2_hi(u.y));
}

__device__ __forceinline__ void mma_f16(float* acc, const uint32_t* a, const uint32_t* b) {
    asm volatile(
        "mma.sync.aligned.m16n8k16.row.col.f32.f16.f16.f32 "
        "{%0,%1,%2,%3}, {%4,%5,%6,%7}, {%8,%9}, {%0,%1,%2,%3};\n"
        : "+f"(acc[0]), "+f"(acc[1]), "+f"(acc[2]), "+f"(acc[3])
        : "r"(a[0]), "r"(a[1]), "r"(a[2]), "r"(a[3]), "r"(b[0]), "r"(b[1]));
}

__device__ __forceinline__ uint32_t sptr(const void* p) {
    return (uint32_t)__cvta_generic_to_shared(p);
}
#define LDSM4(r0, r1, r2, r3, addr)                                              \
    asm volatile("ldmatrix.sync.aligned.m8n8.x4.shared.b16 {%0,%1,%2,%3}, [%4];" \
                 : "=r"(r0), "=r"(r1), "=r"(r2), "=r"(r3) : "r"(addr))

#define EP_SILU 1
#define EP_RES 2
#define EP_MUL 4
#define EP_GNA 8
#define EP_GNRES 16
#define EP_PERM 32
#define EP_HOUT 64  // store output as packed half2 (C is uint32*, 64 words/row)

// ---------------- templated fp16 split tensor-core GEMM, N = 128 --------------
// TM = term count: 3: ah*wh + ah*wl + al*wh ; 2: ah*wh + al*wh ; 1: ah*wh.
struct GD { const float *A, *W, *bias, *res, *mul; float* C; const int* perm; int M, K; };
struct GB3 { GD d[3]; };

#define SAW 12

template <int TM, int F>
__global__ __launch_bounds__(256, 2) void gemm_t(
    GB3 gb, const int* __restrict__ gnb, const float* __restrict__ gcnt,
    const float* __restrict__ gsumP, const float* __restrict__ gsqP)
{
    __shared__ uint32_t AsH[2][128][SAW];
    __shared__ uint32_t AsL[2][128][SAW];
    __shared__ uint32_t WsH[2][128][SAW];
    __shared__ uint32_t WsL[2][128][SAW];

    const GD d = gb.d[blockIdx.y];
    const int row0 = blockIdx.x * 128;

    const int tid = threadIdx.x;
    const int wid = tid >> 5, lane = tid & 31;
    const int g = lane >> 2, tig = lane & 3;
    const int m0 = (wid & 1) * 64, n0 = (wid >> 1) * 32;

    const int arow = tid >> 1, akf = (tid & 1) * 8, akw = (tid & 1) * 4;
    const int wn = tid & 127, wkb = (tid >> 7) * 8, wkw = (tid >> 7) * 4;
    const int a_r = lane & 15, a_kw = (lane >> 4) * 4;
    const int b_nadd = ((lane >> 4) << 3) | (lane & 7), b_kw = ((lane >> 3) & 1) * 4;

    float acc[4][4][4];
#pragma unroll
    for (int mi = 0; mi < 4; mi++)
#pragma unroll
        for (int ni = 0; ni < 4; ni++)
#pragma unroll
            for (int r = 0; r < 4; r++) acc[mi][ni][r] = 0.f;

    const int nc = d.K >> 4;
    const bool arow_ok = (row0 + arow) < d.M;
    const float* aptr = d.A + (size_t)(row0 + arow) * d.K + akf;

    float amean = 0.f, ars = 1.f;
    if constexpr (F & EP_GNA) {
        if (arow_ok) {
            int gg = gnb[row0 + arow];
            float inv = 1.f / (gcnt[gg] * 128.f);
            amean = gsumP[gg] * inv;
            float var = gsqP[gg] * inv - amean * amean;
            ars = rsqrtf(var + 1e-8f);
        }
    }

    float fa[8], fw[8];
    auto fetch = [&](int c) {
        const float* ap = aptr + (size_t)c * 16;
        if (arow_ok) {
            *(float4*)&fa[0] = *(const float4*)ap;
            *(float4*)&fa[4] = *(const float4*)(ap + 4);
        } else {
#pragma unroll
            for (int p = 0; p < 8; p++) fa[p] = 0.f;
        }
        if constexpr (F & EP_GNA) {
#pragma unroll
            for (int p = 0; p < 8; p++) fa[p] = (fa[p] - amean) * ars;
        }
        const float* wp = d.W + (size_t)c * 16 * 128;
#pragma unroll
        for (int j = 0; j < 8; j++) fw[j] = wp[(size_t)(wkb + j) * 128 + wn];
    };
    auto stage = [&](int b) {
        uint32_t h[4], l[4];
#pragma unroll
        for (int p = 0; p < 4; p++) h[p] = pack_h2(fa[2 * p], fa[2 * p + 1]);
        *(uint4*)&AsH[b][arow][akw] = make_uint4(h[0], h[1], h[2], h[3]);
        if constexpr (TM >= 2) {
#pragma unroll
            for (int p = 0; p < 4; p++)
                l[p] = pack_h2(fa[2 * p] - h2_lo(h[p]), fa[2 * p + 1] - h2_hi(h[p]));
            *(uint4*)&AsL[b][arow][akw] = make_uint4(l[0], l[1], l[2], l[3]);
        }
#pragma unroll
        for (int p = 0; p < 4; p++) h[p] = pack_h2(fw[2 * p], fw[2 * p + 1]);
        *(uint4*)&WsH[b][wn][wkw] = make_uint4(h[0], h[1], h[2], h[3]);
        if constexpr (TM == 3) {
#pragma unroll
            for (int p = 0; p < 4; p++)
                l[p] = pack_h2(fw[2 * p] - h2_lo(h[p]), fw[2 * p + 1] - h2_hi(h[p]));
            *(uint4*)&WsL[b][wn][wkw] = make_uint4(l[0], l[1], l[2], l[3]);
        }
    };

    fetch(0);
    stage(0);
    __syncthreads();

    int cur = 0;
    for (int c = 0; c < nc; c++) {
        const bool pf = (c + 1 < nc);
        if (pf) fetch(c + 1);
        uint32_t bH[4][2], bL[4][2];
#pragma unroll
        for (int hh = 0; hh < 2; hh++) {
            int n = n0 + hh * 16 + b_nadd;
            LDSM4(bH[2 * hh][0], bH[2 * hh][1], bH[2 * hh + 1][0], bH[2 * hh + 1][1],
                  sptr(&WsH[cur][n][b_kw]));
            if constexpr (TM == 3)
                LDSM4(bL[2 * hh][0], bL[2 * hh][1], bL[2 * hh + 1][0], bL[2 * hh + 1][1],
                      sptr(&WsL[cur][n][b_kw]));
        }
#pragma unroll
        for (int mi = 0; mi < 4; mi++) {
            int r = m0 + mi * 16 + a_r;
            uint32_t aH[4], aL[4];
            LDSM4(aH[0], aH[1], aH[2], aH[3], sptr(&AsH[cur][r][a_kw]));
            if constexpr (TM >= 2)
                LDSM4(aL[0], aL[1], aL[2], aL[3], sptr(&AsL[cur][r][a_kw]));
#pragma unroll
            for (int ni = 0; ni < 4; ni++) {
                mma_f16(acc[mi][ni], aH, bH[ni]);
                if constexpr (TM == 3) mma_f16(acc[mi][ni], aH, bL[ni]);
                if constexpr (TM >= 2) mma_f16(acc[mi][ni], aL, bH[ni]);
            }
        }
        if (pf) stage(cur ^ 1);
        __syncthreads();
        cur ^= 1;
    }

    // ---- epilogue: (mi, half) outer, per-row params computed once ----
#pragma unroll
    for (int mi = 0; mi < 4; mi++) {
#pragma unroll
        for (int half = 0; half < 2; half++) {
            int r = row0 + m0 + mi * 16 + g + half * 8;
            bool rok = r < d.M;
            float rmean = 0.f, rrs = 1.f;
            if constexpr (F & EP_GNRES) {
                if (rok) {
                    int gg = gnb[r];
                    float inv = 1.f / (gcnt[gg] * 128.f);
                    rmean = gsumP[gg] * inv;
                    float var = gsqP[gg] * inv - rmean * rmean;
                    rrs = rsqrtf(var + 1e-8f);
                }
            }
#pragma unroll
            for (int ni = 0; ni < 4; ni++) {
                int cidx = n0 + ni * 8 + tig * 2;
                float vx = acc[mi][ni][half * 2 + 0];
                float vy = acc[mi][ni][half * 2 + 1];
                if (d.bias) { vx += d.bias[cidx]; vy += d.bias[cidx + 1]; }
                if constexpr (F & EP_SILU) { vx = silu_f(vx); vy = silu_f(vy); }
                if (rok) {
                    size_t off = (size_t)r * 128 + cidx;
                    if constexpr (F & EP_RES) {
                        float2 rr = *(const float2*)(d.res + off);
                        if constexpr (F & EP_GNRES) {
                            rr.x = (rr.x - rmean) * rrs;
                            rr.y = (rr.y - rmean) * rrs;
                        }
                        vx += rr.x; vy += rr.y;
                    }
                    if constexpr (F & EP_MUL) {
                        if (d.mul) {
                            float2 mm = *(const float2*)(d.mul + off);
                            vx *= mm.x; vy *= mm.y;
                        }
                    }
                    size_t orow;
                    if constexpr (F & EP_PERM) orow = (size_t)d.perm[r];
                    else orow = (size_t)r;
                    if constexpr (F & EP_HOUT) {
                        ((uint32_t*)d.C)[orow * 64 + (cidx >> 1)] = pack_h2(vx, vy);
                    } else {
                        *(float2*)(d.C + orow * 128 + cidx) = make_float2(vx, vy);
                    }
                }
            }
        }
    }
}

// ---------------- fp32 weight fold: W' = w2@we, b' = b2@we (per layer) --------
__global__ void fold_we(const float* __restrict__ w2, const float* __restrict__ b2,
                        const float* __restrict__ we, float* __restrict__ Wf,
                        float* __restrict__ Bf) {
    int l = blockIdx.y, r = blockIdx.x, c = threadIdx.x;
    const float* W2 = w2 + (size_t)l * DD * DD;
    const float* WE = we + (size_t)l * DD * DD;
    float s = 0.f;
    for (int k = 0; k < DD; k++) s += W2[r * DD + k] * WE[k * DD + c];
    Wf[(size_t)l * DD * DD + r * DD + c] = s;
    if (r == 0) {
        const float* B2 = b2 + (size_t)l * DD;
        float t = 0.f;
        for (int k = 0; k < DD; k++) t += B2[k] * WE[k * DD + c];
        Bf[(size_t)l * DD + c] = t;
    }
}

// ---------------- CSR construction ----------------
__global__ void hist_seg(const int* __restrict__ idx, int n, int* __restrict__ deg) {
    int t = blockIdx.x * blockDim.x + threadIdx.x;
    if (t >= n) return;
    atomicAdd(&deg[idx[t] + 1], 1);
}

__global__ void scan_offsets(int* __restrict__ deg, int n) {
    __shared__ int wsum[32];
    __shared__ int carry;
    const int lane = threadIdx.x & 31, w = threadIdx.x >> 5;
    if (threadIdx.x == 0) carry = 0;
    __syncthreads();
    for (int base = 0; base < n; base += 1024) {
        int i = base + threadIdx.x;
        int v = (i < n) ? deg[i + 1] : 0;
        int s = v;
#pragma unroll
        for (int o = 1; o < 32; o <<= 1) {
            int t = __shfl_up_sync(0xffffffffu, s, o);
            if (lane >= o) s += t;
        }
        if (lane == 31) wsum[w] = s;
        __syncthreads();
        if (w == 0) {
            int ws = wsum[lane];
#pragma unroll
            for (int o = 1; o < 32; o <<= 1) {
                int t = __shfl_up_sync(0xffffffffu, ws, o);
                if (lane >= o) ws += t;
            }
            wsum[lane] = ws;
        }
        __syncthreads();
        int total = wsum[31];
        int off = carry + (w ? wsum[w - 1] : 0);
        if (i < n) deg[i + 1] = s + off;
        __syncthreads();
        if (threadIdx.x == 0) carry += total;
        __syncthreads();
    }
}

__global__ void fill_csr(const int* __restrict__ idx, int n, int* __restrict__ pos,
                         int* __restrict__ csr, int* __restrict__ pinv) {
    int t = blockIdx.x * blockDim.x + threadIdx.x;
    if (t >= n) return;
    int p = atomicAdd(&pos[idx[t]], 1);
    csr[p] = t;
    if (pinv) pinv[t] = p;
}

__global__ void perm_edges(const int* __restrict__ ecsr, const int* __restrict__ esrc,
                           const int* __restrict__ pai, int* __restrict__ esrc_c,
                           int* __restrict__ pai_c) {
    int j = blockIdx.x * blockDim.x + threadIdx.x;
    if (j >= EE) return;
    int e = ecsr[j];
    esrc_c[j] = esrc[e];
    pai_c[j] = pai[e];
}

// ---------------- dual CSR gather ----------------
struct GPair { const float* src; float* dst; };

__global__ void gather2(GPair p0, GPair p1, const int* __restrict__ off,
                        const int* __restrict__ csr) {
    GPair p = blockIdx.y ? p1 : p0;
    int idx = blockIdx.x * blockDim.x + threadIdx.x;
    int w = idx >> 5, lane = idx & 31;
    if (w >= AA) return;
    int s = off[w], e = off[w + 1];
    float4 acc = make_float4(0, 0, 0, 0);
    for (int j = s; j < e; j++) {
        int n = csr[j];
        float4 v = ((const float4*)(p.src + (size_t)n * DD))[lane];
        acc.x += v.x; acc.y += v.y; acc.z += v.z; acc.w += v.w;
    }
    ((float4*)(p.dst + (size_t)w * DD))[lane] = acc;
}

// ---------------- fused CSR attention: single pass + gate + gn stats ----------
// io holds the per-node gate (rbf@wrbf) on input; overwritten with gated output.
// sw is half2-packed (64 words/row); k, v, ek fp32.
__global__ void attn_csr(const float* __restrict__ q, const float* __restrict__ k,
                         const float* __restrict__ v, const float* __restrict__ ek,
                         const uint32_t* __restrict__ swc, const int* __restrict__ esrc_c,
                         const int* __restrict__ pai_c, const int* __restrict__ off,
                         float* __restrict__ io, const int* __restrict__ nb,
                         float* __restrict__ gs, float* __restrict__ gq) {
    int idx = blockIdx.x * blockDim.x + threadIdx.x;
    int w = idx >> 5, lane = idx & 31;
    if (w >= NN) return;
    int s0 = off[w], s1 = off[w + 1];
    float4 q4 = ((const float4*)(q + (size_t)w * DD))[lane];

    float4 acc = make_float4(0, 0, 0, 0);
    float den = 0.f;
    for (int j = s0; j < s1; j++) {
        int sn = esrc_c[j], pa = pai_c[j];
        float4 k4 = ((const float4*)(k + (size_t)sn * DD))[lane];
        float4 e4 = ((const float4*)(ek + (size_t)pa * DD))[lane];
        float p = q4.x * (k4.x + e4.x) + q4.y * (k4.y + e4.y) +
                  q4.z * (k4.z + e4.z) + q4.w * (k4.w + e4.w);
        p += __shfl_xor_sync(0xffffffffu, p, 1);
        p += __shfl_xor_sync(0xffffffffu, p, 2);
        float ex = expf(p * 0.25f);
        den += ex;
        float4 v4 = ((const float4*)(v + (size_t)sn * DD))[lane];
        float4 s4 = unp4(((const uint2*)(swc + (size_t)j * 64))[lane]);
        acc.x += ex * (v4.x + e4.x) * s4.x;
        acc.y += ex * (v4.y + e4.y) * s4.y;
        acc.z += ex * (v4.z + e4.z) * s4.z;
        acc.w += ex * (v4.w + e4.w) * s4.w;
    }
    float inv = 1.f / (den + 1e-16f);
    float4 g4 = ((const float4*)(io + (size_t)w * DD))[lane];
    float4 o;
    o.x = acc.x * inv * g4.x;
    o.y = acc.y * inv * g4.y;
    o.z = acc.z * inv * g4.z;
    o.w = acc.w * inv * g4.w;
    ((float4*)(io + (size_t)w * DD))[lane] = o;

    float s = o.x + o.y + o.z + o.w;
    float qq = o.x * o.x + o.y * o.y + o.z * o.z + o.w * o.w;
#pragma unroll
    for (int t = 16; t; t >>= 1) {
        s += __shfl_xor_sync(0xffffffffu, s, t);
        qq += __shfl_xor_sync(0xffffffffu, qq, t);
    }
    if (!lane) {
        int gg = nb[w];
        atomicAdd(&gs[gg], s);
        atomicAdd(&gq[gg], qq);
    }
}

// ---------------- misc kernels ----------------
__global__ void count_nodes(const int* __restrict__ batch, float* __restrict__ cnt) {
    int n = blockIdx.x * blockDim.x + threadIdx.x;
    if (n >= NN) return;
    atomicAdd(&cnt[batch[n]], 1.f);
}

__global__ void read_dot(const float* __restrict__ a, const float* __restrict__ w3,
                         const float* __restrict__ b3, float* __restrict__ results) {
    int idx = blockIdx.x * blockDim.x + threadIdx.x;
    int warp = idx >> 5, lane = idx & 31;
    if (warp >= AA) return;
    float4 av = ((const float4*)(a + (size_t)warp * DD))[lane];
    float4 wv = ((const float4*)w3)[lane];
    float s = av.x * wv.x + av.y * wv.y + av.z * wv.z + av.w * wv.w;
#pragma unroll
    for (int o = 16; o; o >>= 1) s += __shfl_xor_sync(0xffffffffu, s, o);
    if (!lane) results[warp] += s + b3[0];
}

__global__ void final_scatter(const float* __restrict__ results, const int* __restrict__ abatch,
                              float* __restrict__ out) {
    int a = blockIdx.x * blockDim.x + threadIdx.x;
    if (a >= AA) return;
    atomicAdd(&out[abatch[a]], results[a] * (1.0f / (float)LL));
}

// ---------------- host orchestration ----------------
static GD mkd(const float* A, const float* W, const float* bias, const float* res,
              const float* mul, float* C, const int* perm, int M, int K) {
    GD d; d.A = A; d.W = W; d.bias = bias; d.res = res; d.mul = mul;
    d.C = C; d.perm = perm; d.M = M; d.K = K; return d;
}

template <int TM, int F>
static void glaunch(const GD& d0, const int* gnb = nullptr, const float* gcnt = nullptr,
                    const float* gs = nullptr, const float* gq = nullptr) {
    GB3 gb; gb.d[0] = d0;
    gemm_t<TM, F><<<dim3((d0.M + 127) / 128, 1), 256>>>(gb, gnb, gcnt, gs, gq);
}
template <int TM, int F>
static void glaunchN(const GD* ds, int n) {
    GB3 gb;
    for (int i = 0; i < n; i++) gb.d[i] = ds[i];
    gemm_t<TM, F><<<dim3((ds[0].M + 127) / 128, n), 256>>>(gb, nullptr, nullptr,
                                                           nullptr, nullptr);
}

extern "C" void kernel_launch(void* const* d_in, const int* in_sizes, int n_in,
                              void* d_out, int out_size) {
    const float* x         = (const float*)d_in[0];
    const float* node_rbf  = (const float*)d_in[1];
    const float* edge_sbf  = (const float*)d_in[2];
    const int*   eidx      = (const int*)d_in[3];
    const int*   pai       = (const int*)d_in[4];
    const int*   idx0      = (const int*)d_in[5];
    const int*   abatch    = (const int*)d_in[6];
    const int*   nbatch    = (const int*)d_in[7];
    const float* edgenn_w1 = (const float*)d_in[8];
    const float* edgenn_b1 = (const float*)d_in[9];
    const float* edgenn_w2 = (const float*)d_in[10];
    const float* edgenn_b2 = (const float*)d_in[11];
    const float* conv_wq   = (const float*)d_in[12];
    const float* conv_wk   = (const float*)d_in[13];
    const float* conv_wv   = (const float*)d_in[14];
    const float* conv_we   = (const float*)d_in[15];
    const float* conv_wsbf = (const float*)d_in[16];
    const float* conv_bsbf = (const float*)d_in[17];
    const float* conv_wrbf = (const float*)d_in[18];
    const float* dense_w   = (const float*)d_in[19];
    const float* dense_b   = (const float*)d_in[20];
    const float* bf_w      = (const float*)d_in[21];
    const float* bf_b      = (const float*)d_in[22];
    const float* af_w      = (const float*)d_in[23];
    const float* af_b      = (const float*)d_in[24];
    const float* read_wrbf = (const float*)d_in[25];
    const float* read_w1   = (const float*)d_in[26];
    const float* read_b1   = (const float*)d_in[27];
    const float* read_w2   = (const float*)d_in[28];
    const float* read_b2   = (const float*)d_in[29];
    const float* read_w3   = (const float*)d_in[30];
    const float* read_b3   = (const float*)d_in[31];

    float *featA, *featB, *featC, *featD, *featE, *featF;
    uint32_t* swh;
    float *at2, *at3, *at4, *at5, *at6, *results, *gsum, *gsq, *gcnt, *wfold, *bfold;
    int *eoff, *epos, *ecsr, *pinv, *esrcc, *paic, *aoff, *apos, *acsr;
    cudaGetSymbolAddress((void**)&featA, g_featA);
    cudaGetSymbolAddress((void**)&featB, g_featB);
    cudaGetSymbolAddress((void**)&featC, g_featC);
    cudaGetSymbolAddress((void**)&featD, g_featD);
    cudaGetSymbolAddress((void**)&featE, g_featE);
    cudaGetSymbolAddress((void**)&featF, g_featF);
    cudaGetSymbolAddress((void**)&swh, g_swh);
    cudaGetSymbolAddress((void**)&at2, g_at2);
    cudaGetSymbolAddress((void**)&at3, g_at3);
    cudaGetSymbolAddress((void**)&at4, g_at4);
    cudaGetSymbolAddress((void**)&at5, g_at5);
    cudaGetSymbolAddress((void**)&at6, g_at6);
    cudaGetSymbolAddress((void**)&results, g_results);
    cudaGetSymbolAddress((void**)&gsum, g_gsum);
    cudaGetSymbolAddress((void**)&gsq, g_gsq);
    cudaGetSymbolAddress((void**)&gcnt, g_gcnt);
    cudaGetSymbolAddress((void**)&wfold, g_wfold);
    cudaGetSymbolAddress((void**)&bfold, g_bfold);
    cudaGetSymbolAddress((void**)&eoff, g_eoff);
    cudaGetSymbolAddress((void**)&epos, g_epos);
    cudaGetSymbolAddress((void**)&ecsr, g_ecsr);
    cudaGetSymbolAddress((void**)&pinv, g_pinv);
    cudaGetSymbolAddress((void**)&esrcc, g_esrcc);
    cudaGetSymbolAddress((void**)&paic, g_paic);
    cudaGetSymbolAddress((void**)&aoff, g_aoff);
    cudaGetSymbolAddress((void**)&apos, g_apos);
    cudaGetSymbolAddress((void**)&acsr, g_acsr);

    cudaMemsetAsync(results, 0, AA * sizeof(float));
    cudaMemsetAsync(gcnt, 0, GG * sizeof(float));
    cudaMemsetAsync(gsum, 0, LL * GG * sizeof(float));
    cudaMemsetAsync(gsq, 0, LL * GG * sizeof(float));
    cudaMemsetAsync(d_out, 0, GG * sizeof(float));
    count_nodes<<<(NN + 255) / 256, 256>>>(nbatch, gcnt);

    // ---- build CSRs ----
    cudaMemsetAsync(eoff, 0, (NN + 1) * sizeof(int));
    hist_seg<<<(EE + 255) / 256, 256>>>(eidx + EE, EE, eoff);
    scan_offsets<<<1, 1024>>>(eoff, NN);
    cudaMemcpyAsync(epos, eoff, NN * sizeof(int), cudaMemcpyDeviceToDevice);
    fill_csr<<<(EE + 255) / 256, 256>>>(eidx + EE, EE, epos, ecsr, pinv);
    perm_edges<<<(EE + 255) / 256, 256>>>(ecsr, eidx, pai, esrcc, paic);

    cudaMemsetAsync(aoff, 0, (AA + 1) * sizeof(int));
    hist_seg<<<(NN + 255) / 256, 256>>>(idx0, NN, aoff);
    scan_offsets<<<1, 1024>>>(aoff, AA);
    cudaMemcpyAsync(apos, aoff, AA * sizeof(int), cudaMemcpyDeviceToDevice);
    fill_csr<<<(NN + 255) / 256, 256>>>(idx0, NN, apos, acsr, (int*)nullptr);

    // ---- fold edgenn_w2 @ conv_we per layer (fp32 exact) ----
    fold_we<<<dim3(DD, LL), DD>>>(edgenn_w2, edgenn_b2, conv_we, wfold, bfold);

    const float* cur = x;

    for (int i = 0; i < LL; i++) {
        size_t dd = (size_t)i * DD * DD;
        float* kt = (cur == featC) ? featD : featC;
        float* gs = gsum + (size_t)i * GG;
        float* gq = gsq + (size_t)i * GG;

        // 1) qkv batched, 2-term: q->featA, k->kt, v->featE
        {
            GD ds[3] = {
                mkd(cur, conv_wq + dd, nullptr, nullptr, nullptr, featA, nullptr, NN, DD),
                mkd(cur, conv_wk + dd, nullptr, nullptr, nullptr, kt, nullptr, NN, DD),
                mkd(cur, conv_wv + dd, nullptr, nullptr, nullptr, featE, nullptr, NN, DD)};
            glaunchN<2, 0>(ds, 3);
        }
        // 2) sbf (1-term, CSR-permuted rows, half2 output) -> swh
        glaunch<1, EP_PERM | EP_HOUT>(
            mkd(edge_sbf, conv_wsbf + (size_t)i * SBFD * DD, conv_bsbf + (size_t)i * DD,
                nullptr, nullptr, (float*)swh, pinv, EE, SBFD));
        // 3) gates batched (K=16): wrbf gate -> featB ; readout gate (*cur) -> featF
        {
            GD ds[2] = {
                mkd(node_rbf, conv_wrbf + (size_t)i * RBFD * DD, nullptr, nullptr,
                    nullptr, featB, nullptr, NN, RBFD),
                mkd(node_rbf, read_wrbf + (size_t)i * RBFD * DD, nullptr, nullptr,
                    cur, featF, nullptr, NN, RBFD)};
            glaunchN<3, EP_MUL>(ds, 2);
        }
        // 4) dual gather: cur -> at6 (edge path), featF -> at4 (readout)
        {
            GPair p0 = {cur, at6}, p1 = {featF, at4};
            gather2<<<dim3((AA * 32 + 255) / 256, 2), 256>>>(p0, p1, aoff, acsr);
        }
        // 5) AA batch: edgenn_w1 -> at2 ; read_w1 -> at5 (both SILU)
        {
            GD ds[2] = {
                mkd(at6, edgenn_w1 + dd, edgenn_b1 + (size_t)i * DD, nullptr, nullptr,
                    at2, nullptr, AA, DD),
                mkd(at4, read_w1 + (size_t)i * DD * DD, read_b1 + (size_t)i * DD,
                    nullptr, nullptr, at5, nullptr, AA, DD)};
            glaunchN<3, EP_SILU>(ds, 2);
        }
        // 6) wfold (plain) -> at3 (= ek) ; read_w2 (SILU) -> at6 ; dot(w3) -> results
        glaunch<3, 0>(mkd(at2, wfold + dd, bfold + (size_t)i * DD, nullptr, nullptr,
                          at3, nullptr, AA, DD));
        glaunch<3, EP_SILU>(mkd(at5, read_w2 + (size_t)i * DD * DD,
                                read_b2 + (size_t)i * DD, nullptr, nullptr, at6,
                                nullptr, AA, DD));
        read_dot<<<(AA * 32 + 255) / 256, 256>>>(at6, read_w3 + (size_t)i * DD,
                                                 read_b3 + i, results);
        // 7) attention (gate mul + gn stats fused) -> featB in place
        attn_csr<<<(NN * 32 + 255) / 256, 256>>>(featA, kt, featE, at3, swh,
                                                 esrcc, paic, eoff, featB, nbatch, gs, gq);
        // 8) residual chain (gn fused: bf1 fetch, bf2 residual)
        glaunch<3, EP_SILU | EP_GNA>(
            mkd(featB, bf_w + (size_t)(i * 2 + 0) * DD * DD, bf_b + (size_t)(i * 2 + 0) * DD,
                nullptr, nullptr, kt, nullptr, NN, DD), nbatch, gcnt, gs, gq);
        glaunch<3, EP_SILU | EP_RES | EP_GNRES>(
            mkd(kt, bf_w + (size_t)(i * 2 + 1) * DD * DD, bf_b + (size_t)(i * 2 + 1) * DD,
                featB, nullptr, featB, nullptr, NN, DD), nbatch, gcnt, gs, gq);
        glaunch<3, EP_SILU | EP_RES>(
            mkd(featB, dense_w + dd, dense_b + (size_t)i * DD, cur, nullptr, kt,
                nullptr, NN, DD));
        glaunch<3, EP_SILU>(
            mkd(kt, af_w + (size_t)(i * 4 + 0) * DD * DD, af_b + (size_t)(i * 4 + 0) * DD,
                nullptr, nullptr, featB, nullptr, NN, DD));
        glaunch<3, EP_SILU | EP_RES>(
            mkd(featB, af_w + (size_t)(i * 4 + 1) * DD * DD, af_b + (size_t)(i * 4 + 1) * DD,
                kt, nullptr, kt, nullptr, NN, DD));
        glaunch<3, EP_SILU>(
            mkd(kt, af_w + (size_t)(i * 4 + 2) * DD * DD, af_b + (size_t)(i * 4 + 2) * DD,
                nullptr, nullptr, featB, nullptr, NN, DD));
        glaunch<3, EP_SILU | EP_RES>(
            mkd(featB, af_w + (size_t)(i * 4 + 3) * DD * DD, af_b + (size_t)(i * 4 + 3) * DD,
                kt, nullptr, kt, nullptr, NN, DD));
        cur = kt;
    }

    // ---- final readout(LL) ----
    glaunch<3, EP_MUL>(mkd(node_rbf, read_wrbf + (size_t)LL * RBFD * DD, nullptr,
                           nullptr, cur, featF, nullptr, NN, RBFD));
    {
        GPair p0 = {featF, at4}, p1 = {featF, at4};
        gather2<<<dim3((AA * 32 + 255) / 256, 1), 256>>>(p0, p1, aoff, acsr);
    }
    glaunch<3, EP_SILU>(mkd(at4, read_w1 + (size_t)LL * DD * DD,
                            read_b1 + (size_t)LL * DD, nullptr, nullptr, at5,
                            nullptr, AA, DD));
    glaunch<3, EP_SILU>(mkd(at5, read_w2 + (size_t)LL * DD * DD,
                            read_b2 + (size_t)LL * DD, nullptr, nullptr, at6,
                            nullptr, AA, DD));
    read_dot<<<(AA * 32 + 255) / 256, 256>>>(at6, read_w3 + (size_t)LL * DD,
                                             read_b3 + LL, results);

    final_scatter<<<(AA + 255) / 256, 256>>>(results, abatch, (float*)d_out);
}